// round 7
// baseline (speedup 1.0000x reference)
#include <cuda_runtime.h>
#include <cuda_bf16.h>
#include <cstdint>

#define B_SZ 16384
#define FDIM 2048
#define HID  256
#define NN   9
#define BROWS (B_SZ * NN)   /* 147456 */

// ---------------- scratch (static device globals; no allocations) ----------
__device__ __align__(256) __nv_bfloat16 g_Xhi[(size_t)B_SZ * FDIM];        // conc hi
__device__ __align__(256) __nv_bfloat16 g_Xlo[(size_t)B_SZ * FDIM];        // conc lo
__device__ __align__(256) __nv_bfloat16 g_nshi[(size_t)BROWS * HID];       // node states hi
__device__ __align__(256) __nv_bfloat16 g_nslo[(size_t)BROWS * HID];       // node states lo
__device__ __align__(256) __nv_bfloat16 g_W1hi[(size_t)(NN * HID) * FDIM]; // f2n_w hi
__device__ __align__(256) __nv_bfloat16 g_W1lo[(size_t)(NN * HID) * FDIM];
__device__ __align__(256) __nv_bfloat16 g_W2hi[512 * 256];                 // Wc2 hi (rearranged)
__device__ __align__(256) __nv_bfloat16 g_W2lo[512 * 256];                 // Wc2 lo
__device__ __align__(256) float g_Wc[512 * 256];                           // rearranged [U1;U2*msg_w]
__device__ __align__(256) float g_part[2][4][B_SZ];                        // partial output dots
__device__ float g_c[256];                                                 // U2*msg_b + upd_b

// ---------------- PTX helpers (baseline sm_80/sm_100 features only) --------
static __device__ __forceinline__ uint32_t smem_u32(const void* p) {
    uint32_t a;
    asm("{ .reg .u64 t; cvta.to.shared.u64 t, %1; cvt.u32.u64 %0, t; }" : "=r"(a) : "l"(p));
    return a;
}
static __device__ __forceinline__ void cp16(uint32_t s, const void* g) {
    asm volatile("cp.async.cg.shared.global [%0], [%1], 16;" :: "r"(s), "l"(g));
}
static __device__ __forceinline__ void cp_commit() { asm volatile("cp.async.commit_group;"); }
template<int N> static __device__ __forceinline__ void cp_wait() {
    asm volatile("cp.async.wait_group %0;" :: "n"(N));
}
#define LDMX4(r0, r1, r2, r3, a) \
    asm volatile("ldmatrix.sync.aligned.m8n8.x4.shared.b16 {%0,%1,%2,%3}, [%4];" \
        : "=r"(r0), "=r"(r1), "=r"(r2), "=r"(r3) : "r"(a))
#define MMA(c, a, b) \
    asm volatile("mma.sync.aligned.m16n8k16.row.col.f32.bf16.bf16.f32 " \
        "{%0,%1,%2,%3},{%4,%5,%6,%7},{%8,%9},{%0,%1,%2,%3};" \
        : "+f"((c)[0]), "+f"((c)[1]), "+f"((c)[2]), "+f"((c)[3]) \
        : "r"((a)[0]), "r"((a)[1]), "r"((a)[2]), "r"((a)[3]), "r"((b)[0]), "r"((b)[1]))

static __device__ __forceinline__ uint32_t pack_bf2(__nv_bfloat16 a, __nv_bfloat16 b) {
    return (uint32_t)__bfloat16_as_ushort(a) | ((uint32_t)__bfloat16_as_ushort(b) << 16);
}

// ---------------- setup: rearranged Wc2, c = U2*msg_b + upd_b --------------
// Wc row o (U1 row o if o<256, else W2 row o-256 where W2 = U2 @ msg_w).
// Rearranged row: U1 row o -> (o>>6)*128 + (o&63); W2 row o' -> (o'>>6)*128 + 64 + (o'&63).
// So N-tile t (128 B-rows) = h-slice [t*64, t*64+64) of BOTH U1 (cols 0:64) and W2 (cols 64:128).
__global__ void setup_kernel(const float* __restrict__ upd_w,
                             const float* __restrict__ msg_w,
                             const float* __restrict__ upd_b,
                             const float* __restrict__ msg_b) {
    int o = blockIdx.x;
    int k = threadIdx.x;  // 256
    if (o < 256) {
        int nr = (o >> 6) * 128 + (o & 63);
        g_Wc[nr * 256 + k] = upd_w[o * 512 + k];
    } else if (o < 512) {
        int oo = o - 256;
        float s = 0.f;
        #pragma unroll 8
        for (int t = 0; t < 256; ++t)
            s = fmaf(upd_w[oo * 512 + 256 + t], msg_w[t * 256 + k], s);
        int nr = (oo >> 6) * 128 + 64 + (oo & 63);
        g_Wc[nr * 256 + k] = s;
    } else {
        float s = upd_b[k];
        for (int t = 0; t < 256; ++t)
            s = fmaf(upd_w[k * 512 + 256 + t], msg_b[t], s);
        g_c[k] = s;
    }
}

// ---------------- split fp32 -> (bf16 hi, bf16 lo) -------------------------
__global__ void split_kernel(const float* __restrict__ x, __nv_bfloat16* __restrict__ hi,
                             __nv_bfloat16* __restrict__ lo, int n4) {
    int i = blockIdx.x * blockDim.x + threadIdx.x;
    if (i >= n4) return;
    float4 v = ((const float4*)x)[i];
    __nv_bfloat16 h0 = __float2bfloat16(v.x), h1 = __float2bfloat16(v.y);
    __nv_bfloat16 h2 = __float2bfloat16(v.z), h3 = __float2bfloat16(v.w);
    uint2 ph, pl;
    ph.x = pack_bf2(h0, h1);
    ph.y = pack_bf2(h2, h3);
    pl.x = pack_bf2(__float2bfloat16(v.x - __bfloat162float(h0)),
                    __float2bfloat16(v.y - __bfloat162float(h1)));
    pl.y = pack_bf2(__float2bfloat16(v.z - __bfloat162float(h2)),
                    __float2bfloat16(v.w - __bfloat162float(h3)));
    ((uint2*)hi)[i] = ph;
    ((uint2*)lo)[i] = pl;
}

// ================= GEMM 1: conc @ f2n_w^T + biases -> split-bf16 ns ========
// 3-pass split-bf16 on mma.sync, CTA tile 128x128, BK=32, 3-stage cp.async.
#define PITCH1   80
#define TILE1   (128 * PITCH1)
#define STAGE1  (4 * TILE1)          /* Ahi,Alo,Bhi,Blo */
#define SMEM1   (3 * STAGE1)         /* 122880 */

__global__ __launch_bounds__(256)
void gemm1(const __nv_bfloat16* __restrict__ Ahi, const __nv_bfloat16* __restrict__ Alo,
           const __nv_bfloat16* __restrict__ Bhi, const __nv_bfloat16* __restrict__ Blo,
           __nv_bfloat16* __restrict__ nshi, __nv_bfloat16* __restrict__ nslo,
           const float* __restrict__ colBias, const float* __restrict__ hBias,
           const float* __restrict__ hScale, const float* __restrict__ logits) {
    extern __shared__ char smem_raw[];
    const uint32_t sbase = smem_u32(smem_raw);
    const int K = FDIM;
    const int tid = threadIdx.x;
    const int wid = tid >> 5, lane = tid & 31;
    const int m0 = blockIdx.y * 128;
    const int n0 = blockIdx.x * 128;
    const int m_w = (wid & 1) * 64;
    const int n_w = (wid >> 1) * 32;

    const __nv_bfloat16* gT[4] = { Ahi + (size_t)m0 * K, Alo + (size_t)m0 * K,
                                   Bhi + (size_t)n0 * K, Blo + (size_t)n0 * K };

    const int aRow  = m_w + (lane & 15);
    const int aColB = (lane >> 4) << 4;
    const int bRow  = n_w + ((lane >> 4) << 3) + (lane & 7);
    const int bColB = ((lane >> 3) & 1) << 4;

    float acc[4][4][4];
    #pragma unroll
    for (int a = 0; a < 4; ++a)
        #pragma unroll
        for (int b = 0; b < 4; ++b)
            #pragma unroll
            for (int c = 0; c < 4; ++c) acc[a][b][c] = 0.f;

    const int nchunk = K >> 5;   // 64

    auto load_chunk = [&](int kt, int s) {
        uint32_t st = sbase + (uint32_t)s * STAGE1;
        int k0 = kt * 32;
        #pragma unroll
        for (int t4 = 0; t4 < 4; ++t4) {
            const __nv_bfloat16* g = gT[t4];
            uint32_t tb = st + t4 * TILE1;
            #pragma unroll
            for (int i = 0; i < 2; ++i) {
                int id = tid + i * 256;
                int r = id >> 2, ch = id & 3;
                cp16(tb + (uint32_t)(r * PITCH1 + ch * 16), g + (size_t)r * K + k0 + ch * 8);
            }
        }
        cp_commit();
    };

    load_chunk(0, 0);
    load_chunk(1, 1);
    load_chunk(2, 2);

    for (int kt = 0; kt < nchunk; ++kt) {
        const int s = kt % 3;
        if (kt + 2 < nchunk) cp_wait<2>();
        else if (kt + 1 < nchunk) cp_wait<1>();
        else cp_wait<0>();
        __syncthreads();

        const uint32_t st  = sbase + (uint32_t)s * STAGE1;
        const uint32_t tAh = st, tAl = st + TILE1, tBh = st + 2 * TILE1, tBl = st + 3 * TILE1;

        #pragma unroll
        for (int kb = 0; kb < 2; ++kb) {
            const uint32_t aoff = (uint32_t)(kb * 32 + aColB);
            const uint32_t boff = (uint32_t)(kb * 32 + bColB);
            uint32_t ah[4][4], al[4][4], bh[8], bl[8];

            #pragma unroll
            for (int mb = 0; mb < 4; ++mb)
                LDMX4(ah[mb][0], ah[mb][1], ah[mb][2], ah[mb][3],
                      tAh + (uint32_t)((aRow + mb * 16) * PITCH1) + aoff);
            LDMX4(bh[0], bh[1], bh[2], bh[3], tBh + (uint32_t)(bRow * PITCH1) + boff);
            LDMX4(bh[4], bh[5], bh[6], bh[7], tBh + (uint32_t)((bRow + 16) * PITCH1) + boff);
            #pragma unroll
            for (int mb = 0; mb < 4; ++mb)
                #pragma unroll
                for (int nb = 0; nb < 4; ++nb)
                    MMA(acc[mb][nb], ah[mb], &bh[nb * 2]);

            LDMX4(bl[0], bl[1], bl[2], bl[3], tBl + (uint32_t)(bRow * PITCH1) + boff);
            LDMX4(bl[4], bl[5], bl[6], bl[7], tBl + (uint32_t)((bRow + 16) * PITCH1) + boff);
            #pragma unroll
            for (int mb = 0; mb < 4; ++mb)
                #pragma unroll
                for (int nb = 0; nb < 4; ++nb)
                    MMA(acc[mb][nb], ah[mb], &bl[nb * 2]);

            #pragma unroll
            for (int mb = 0; mb < 4; ++mb)
                LDMX4(al[mb][0], al[mb][1], al[mb][2], al[mb][3],
                      tAl + (uint32_t)((aRow + mb * 16) * PITCH1) + aoff);
            #pragma unroll
            for (int mb = 0; mb < 4; ++mb)
                #pragma unroll
                for (int nb = 0; nb < 4; ++nb)
                    MMA(acc[mb][nb], al[mb], &bh[nb * 2]);
        }

        __syncthreads();
        if (kt + 3 < nchunk) load_chunk(kt + 3, s);
    }

    // ---- epilogue: fused biases, split bf16 -> nshi/nslo ----
    const int g  = lane >> 2;
    const int t2 = (lane & 3) * 2;
    const int node = n0 >> 8;
    #pragma unroll
    for (int mb = 0; mb < 4; ++mb) {
        const int r0 = m0 + m_w + mb * 16 + g;
        const int r1 = r0 + 8;
        const float lg0 = logits[(size_t)r0 * NN + node];
        const float lg1 = logits[(size_t)r1 * NN + node];
        const size_t base0 = ((size_t)r0 * NN + node) * 256;
        const size_t base1 = ((size_t)r1 * NN + node) * 256;
        #pragma unroll
        for (int nb = 0; nb < 4; ++nb) {
            const int col = n0 + n_w + nb * 8 + t2;
            const int h = col & 255;
            const float cb0 = colBias[col] + hBias[h];
            const float cb1 = colBias[col + 1] + hBias[h + 1];
            const float s0 = hScale[h], s1 = hScale[h + 1];
            float v00 = acc[mb][nb][0] + cb0 + lg0 * s0;
            float v01 = acc[mb][nb][1] + cb1 + lg0 * s1;
            float v10 = acc[mb][nb][2] + cb0 + lg1 * s0;
            float v11 = acc[mb][nb][3] + cb1 + lg1 * s1;
            __nv_bfloat16 e00 = __float2bfloat16(v00), e01 = __float2bfloat16(v01);
            __nv_bfloat16 e10 = __float2bfloat16(v10), e11 = __float2bfloat16(v11);
            *(uint32_t*)&nshi[base0 + h] = pack_bf2(e00, e01);
            *(uint32_t*)&nslo[base0 + h] = pack_bf2(__float2bfloat16(v00 - __bfloat162float(e00)),
                                                    __float2bfloat16(v01 - __bfloat162float(e01)));
            *(uint32_t*)&nshi[base1 + h] = pack_bf2(e10, e11);
            *(uint32_t*)&nslo[base1 + h] = pack_bf2(__float2bfloat16(v10 - __bfloat162float(e10)),
                                                    __float2bfloat16(v11 - __bfloat162float(e11)));
        }
    }
}

// ================= fused step: GEMM + adjacency mix + tanh =================
// M-tile 144 rows (= 16 batches x 9 nodes), N-tile 128 (= h-slice 64 of Y1 & Z),
// K=256, BK=64, 2-stage. 288 threads = 9 warps; warp w -> m-block w (16 rows x 128 cols).
// FIN=0: write split-bf16 ns. FIN=1: partial output dots -> g_part.
#define SP      144                  /* smem row pitch bytes (64 bf16 + 16 pad) */
#define ATILE2  (144 * SP)           /* 20736 */
#define BTILE2  (128 * SP)           /* 18432 */
#define STAGE2  (2 * ATILE2 + 2 * BTILE2)  /* 78336 */
#define SMEM2   (2 * STAGE2)         /* 156672 */
#define EP      130                  /* epilogue fp32 pitch (floats) */

template<int FIN>
__global__ __launch_bounds__(288)
void step_kernel(const __nv_bfloat16* __restrict__ Ahi, const __nv_bfloat16* __restrict__ Alo,
                 const __nv_bfloat16* __restrict__ Bhi, const __nv_bfloat16* __restrict__ Blo,
                 __nv_bfloat16* __restrict__ nshi, __nv_bfloat16* __restrict__ nslo,
                 const float* __restrict__ out_w) {
    extern __shared__ char smem_raw[];
    const uint32_t sbase = smem_u32(smem_raw);
    float* sm = (float*)smem_raw;

    const int tid = threadIdx.x;
    const int wid = tid >> 5, lane = tid & 31;
    const int t  = blockIdx.x;           // h-tile 0..3
    const int b0 = blockIdx.y * 16;      // first batch
    const int m0 = b0 * NN;              // first A row (144-row tile)

    const __nv_bfloat16* gAh = Ahi + (size_t)m0 * 256;
    const __nv_bfloat16* gAl = Alo + (size_t)m0 * 256;
    const __nv_bfloat16* gBh = Bhi + (size_t)(t * 128) * 256;
    const __nv_bfloat16* gBl = Blo + (size_t)(t * 128) * 256;

    const int aRow  = wid * 16 + (lane & 15);
    const int aColB = (lane >> 4) << 4;
    const int bRowP = ((lane >> 4) << 3) + (lane & 7);
    const int bColB = ((lane >> 3) & 1) << 4;

    float acc[16][4];
    #pragma unroll
    for (int nb = 0; nb < 16; ++nb)
        #pragma unroll
        for (int c = 0; c < 4; ++c) acc[nb][c] = 0.f;

    auto load_chunk = [&](int kt, int s) {
        uint32_t st = sbase + (uint32_t)s * STAGE2;
        int k0 = kt * 64;
        // A hi/lo: 144 rows x 8 chunks = 1152 cp16 each (288*4)
        #pragma unroll
        for (int i = 0; i < 4; ++i) {
            int id = tid + i * 288;
            int r = id >> 3, ch = id & 7;
            cp16(st + (uint32_t)(r * SP + ch * 16), gAh + (size_t)r * 256 + k0 + ch * 8);
            cp16(st + ATILE2 + (uint32_t)(r * SP + ch * 16), gAl + (size_t)r * 256 + k0 + ch * 8);
        }
        // B hi/lo: 128 rows x 8 chunks = 1024 cp16 each
        for (int id = tid; id < 1024; id += 288) {
            int r = id >> 3, ch = id & 7;
            cp16(st + 2 * ATILE2 + (uint32_t)(r * SP + ch * 16), gBh + (size_t)r * 256 + k0 + ch * 8);
            cp16(st + 2 * ATILE2 + BTILE2 + (uint32_t)(r * SP + ch * 16), gBl + (size_t)r * 256 + k0 + ch * 8);
        }
        cp_commit();
    };

    load_chunk(0, 0);
    load_chunk(1, 1);

    for (int kt = 0; kt < 4; ++kt) {
        const int s = kt & 1;
        if (kt + 1 < 4) cp_wait<1>(); else cp_wait<0>();
        __syncthreads();

        const uint32_t st  = sbase + (uint32_t)s * STAGE2;
        const uint32_t tAh = st, tAl = st + ATILE2;
        const uint32_t tBh = st + 2 * ATILE2, tBl = tBh + BTILE2;

        #pragma unroll
        for (int kk = 0; kk < 4; ++kk) {
            const uint32_t aoff = (uint32_t)(kk * 32 + aColB);
            const uint32_t boff = (uint32_t)(kk * 32 + bColB);
            uint32_t ah[4], al[4], bh[8][4], bl[8][4];

            LDMX4(ah[0], ah[1], ah[2], ah[3], tAh + (uint32_t)(aRow * SP) + aoff);
            #pragma unroll
            for (int gg = 0; gg < 8; ++gg)
                LDMX4(bh[gg][0], bh[gg][1], bh[gg][2], bh[gg][3],
                      tBh + (uint32_t)((gg * 16 + bRowP) * SP) + boff);
            #pragma unroll
            for (int nb = 0; nb < 16; ++nb)
                MMA(acc[nb], ah, &bh[nb >> 1][(nb & 1) * 2]);

            #pragma unroll
            for (int gg = 0; gg < 8; ++gg)
                LDMX4(bl[gg][0], bl[gg][1], bl[gg][2], bl[gg][3],
                      tBl + (uint32_t)((gg * 16 + bRowP) * SP) + boff);
            #pragma unroll
            for (int nb = 0; nb < 16; ++nb)
                MMA(acc[nb], ah, &bl[nb >> 1][(nb & 1) * 2]);

            LDMX4(al[0], al[1], al[2], al[3], tAl + (uint32_t)(aRow * SP) + aoff);
            #pragma unroll
            for (int nb = 0; nb < 16; ++nb)
                MMA(acc[nb], al, &bh[nb >> 1][(nb & 1) * 2]);
        }

        __syncthreads();
        if (kt + 2 < 4) load_chunk(kt + 2, s);
    }

    // ---- dump accumulators to SMEM: tile [144][EP] fp32 (Y1 cols 0:64, Z cols 64:128)
    {
        const int r = wid * 16 + (lane >> 2);
        const int c = (lane & 3) * 2;
        #pragma unroll
        for (int nb = 0; nb < 16; ++nb) {
            const int col = nb * 8 + c;
            sm[r * EP + col]       = acc[nb][0];
            sm[r * EP + col + 1]   = acc[nb][1];
            sm[(r + 8) * EP + col]     = acc[nb][2];
            sm[(r + 8) * EP + col + 1] = acc[nb][3];
        }
    }
    __syncthreads();

    // ---- combine: for each (b_local, h_local) mix 9 nodes, tanh ----
    float* sm2 = sm + 144 * EP;   // FIN scratch: [2][1024]
    for (int idx = tid; idx < 1024; idx += 288) {
        const int bl_ = idx >> 6;
        const int hl  = idx & 63;
        const int hg  = t * 64 + hl;
        const float cb = g_c[hg];
        const float* rowp = sm + (bl_ * NN) * EP;
        float z[NN], total = 0.f;
        #pragma unroll
        for (int j = 0; j < NN; ++j) { z[j] = rowp[j * EP + 64 + hl]; total += z[j]; }
        const float s78 = (total - z[1]) * 0.125f;

        if (FIN == 0) {
            float pre[NN];
            pre[0] = rowp[0 * EP + hl] + total * (1.f / 9.f) + cb;
            pre[1] = rowp[1 * EP + hl] + (z[0] + z[1]) * 0.5f + cb;
            #pragma unroll
            for (int i = 2; i < 7; ++i)
                pre[i] = rowp[i * EP + hl] + (z[0] + z[i] + z[7] + z[8]) * 0.25f + cb;
            pre[7] = rowp[7 * EP + hl] + s78 + cb;
            pre[8] = rowp[8 * EP + hl] + s78 + cb;
            const size_t base = ((size_t)(b0 + bl_) * NN) * 256 + hg;
            #pragma unroll
            for (int i = 0; i < NN; ++i) {
                float v = tanhf(pre[i]);
                __nv_bfloat16 e = __float2bfloat16(v);
                nshi[base + i * 256] = e;
                nslo[base + i * 256] = __float2bfloat16(v - __bfloat162float(e));
            }
        } else {
            const float ow = out_w[hg];
            sm2[idx]        = tanhf(rowp[7 * EP + hl] + s78 + cb) * ow;
            sm2[1024 + idx] = tanhf(rowp[8 * EP + hl] + s78 + cb) * ow;
        }
    }
    if (FIN == 1) {
        __syncthreads();
        if (tid < 32) {
            const int bl_ = tid >> 1, node = tid & 1;
            const float* p = sm2 + node * 1024 + bl_ * 64;
            float s = 0.f;
            #pragma unroll
            for (int h = 0; h < 64; ++h) s += p[h];
            g_part[node][t][b0 + bl_] = s;
        }
    }
}

// ---------------- final reduce: out = out_b + sum_t part ------------------
__global__ void reduce_kernel(const float* __restrict__ out_b, float* __restrict__ out) {
    int idx = blockIdx.x * blockDim.x + threadIdx.x;
    if (idx >= 2 * B_SZ) return;
    int node = idx >> 14;           // /16384
    int b = idx & (B_SZ - 1);
    out[idx] = out_b[0] + g_part[node][0][b] + g_part[node][1][b]
             + g_part[node][2][b] + g_part[node][3][b];
}

// ---------------- launch ---------------------------------------------------
extern "C" void kernel_launch(void* const* d_in, const int* in_sizes, int n_in,
                              void* d_out, int out_size) {
    const float* conc   = (const float*)d_in[0];   // [B, 2048]
    const float* logits = (const float*)d_in[1];   // [B, 9]
    const float* enc_w  = (const float*)d_in[2];   // [256, 1]
    const float* enc_b  = (const float*)d_in[3];   // [256]
    const float* f2n_w  = (const float*)d_in[4];   // [2304, 2048]
    const float* f2n_b  = (const float*)d_in[5];   // [2304]
    const float* msg_w  = (const float*)d_in[6];   // [256, 256]
    const float* msg_b  = (const float*)d_in[7];   // [256]
    const float* upd_w  = (const float*)d_in[8];   // [256, 512]
    const float* upd_b  = (const float*)d_in[9];   // [256]
    const float* out_w  = (const float*)d_in[10];  // [1, 256]
    const float* out_b  = (const float*)d_in[11];  // [1]
    float* out = (float*)d_out;

    __nv_bfloat16 *Xhi, *Xlo, *nshi, *nslo, *W1hi, *W1lo, *W2hi, *W2lo;
    float *Wc;
    cudaGetSymbolAddress((void**)&Xhi,  g_Xhi);
    cudaGetSymbolAddress((void**)&Xlo,  g_Xlo);
    cudaGetSymbolAddress((void**)&nshi, g_nshi);
    cudaGetSymbolAddress((void**)&nslo, g_nslo);
    cudaGetSymbolAddress((void**)&W1hi, g_W1hi);
    cudaGetSymbolAddress((void**)&W1lo, g_W1lo);
    cudaGetSymbolAddress((void**)&W2hi, g_W2hi);
    cudaGetSymbolAddress((void**)&W2lo, g_W2lo);
    cudaGetSymbolAddress((void**)&Wc,   g_Wc);

    cudaFuncSetAttribute((const void*)gemm1, cudaFuncAttributeMaxDynamicSharedMemorySize, SMEM1);
    cudaFuncSetAttribute((const void*)step_kernel<0>, cudaFuncAttributeMaxDynamicSharedMemorySize, SMEM2);
    cudaFuncSetAttribute((const void*)step_kernel<1>, cudaFuncAttributeMaxDynamicSharedMemorySize, SMEM2);

    // fold + rearrange weights, then split to bf16 hi/lo
    setup_kernel<<<513, 256>>>(upd_w, msg_w, upd_b, msg_b);
    int n4 = (B_SZ * FDIM) / 4;
    split_kernel<<<(n4 + 255) / 256, 256>>>(conc, Xhi, Xlo, n4);
    n4 = (NN * HID * FDIM) / 4;
    split_kernel<<<(n4 + 255) / 256, 256>>>(f2n_w, W1hi, W1lo, n4);
    n4 = (512 * 256) / 4;
    split_kernel<<<(n4 + 255) / 256, 256>>>(Wc, W2hi, W2lo, n4);

    // ns = conc @ f2n_w^T + biases  -> split-bf16 node states [B*9, 256]
    gemm1<<<dim3((NN * HID) / 128, B_SZ / 128), 256, SMEM1>>>(
        Xhi, Xlo, W1hi, W1lo, nshi, nslo, f2n_b, enc_b, enc_w, logits);

    // 4 fused message-passing steps (Y never hits DRAM)
    step_kernel<0><<<dim3(4, BROWS / 144), 288, SMEM2>>>(nshi, nslo, W2hi, W2lo, nshi, nslo, nullptr);
    step_kernel<0><<<dim3(4, BROWS / 144), 288, SMEM2>>>(nshi, nslo, W2hi, W2lo, nshi, nslo, nullptr);
    step_kernel<0><<<dim3(4, BROWS / 144), 288, SMEM2>>>(nshi, nslo, W2hi, W2lo, nshi, nslo, nullptr);
    step_kernel<1><<<dim3(4, BROWS / 144), 288, SMEM2>>>(nshi, nslo, W2hi, W2lo, nshi, nslo, out_w);

    reduce_kernel<<<(2 * B_SZ + 255) / 256, 256>>>(out_b, out);
}

// round 8
// speedup vs baseline: 1.2626x; 1.2626x over previous
#include <cuda_runtime.h>
#include <cuda_bf16.h>
#include <cstdint>

#define B_SZ 16384
#define FDIM 2048
#define HID  256
#define NN   9
#define BROWS (B_SZ * NN)   /* 147456 */

// ---------------- scratch (static device globals; no allocations) ----------
__device__ __align__(256) __nv_bfloat16 g_Xhi[(size_t)B_SZ * FDIM];        // conc hi
__device__ __align__(256) __nv_bfloat16 g_Xlo[(size_t)B_SZ * FDIM];        // conc lo
__device__ __align__(256) __nv_bfloat16 g_nshi[(size_t)BROWS * HID];       // node states hi
__device__ __align__(256) __nv_bfloat16 g_nslo[(size_t)BROWS * HID];       // node states lo
__device__ __align__(256) __nv_bfloat16 g_W1hi[(size_t)(NN * HID) * FDIM]; // f2n_w hi
__device__ __align__(256) __nv_bfloat16 g_W1lo[(size_t)(NN * HID) * FDIM];
__device__ __align__(256) __nv_bfloat16 g_W2hi[512 * 256];                 // Wc hi
__device__ __align__(256) __nv_bfloat16 g_W2lo[512 * 256];                 // Wc lo
__device__ __align__(256) float g_Y[(size_t)BROWS * 512];                  // step GEMM out
__device__ __align__(256) float g_Wc[512 * 256];                           // [U1 ; U2*msg_w]
__device__ float g_c[256];                                                 // U2*msg_b + upd_b

// ---------------- PTX helpers (baseline sm_80/sm_100 features only) --------
static __device__ __forceinline__ uint32_t smem_u32(const void* p) {
    uint32_t a;
    asm("{ .reg .u64 t; cvta.to.shared.u64 t, %1; cvt.u32.u64 %0, t; }" : "=r"(a) : "l"(p));
    return a;
}
static __device__ __forceinline__ void cp16(uint32_t s, const void* g) {
    asm volatile("cp.async.cg.shared.global [%0], [%1], 16;" :: "r"(s), "l"(g));
}
static __device__ __forceinline__ void cp_commit() { asm volatile("cp.async.commit_group;"); }
template<int N> static __device__ __forceinline__ void cp_wait() {
    asm volatile("cp.async.wait_group %0;" :: "n"(N));
}
#define LDMX4(r0, r1, r2, r3, a) \
    asm volatile("ldmatrix.sync.aligned.m8n8.x4.shared.b16 {%0,%1,%2,%3}, [%4];" \
        : "=r"(r0), "=r"(r1), "=r"(r2), "=r"(r3) : "r"(a))
#define MMA(c, a, b) \
    asm volatile("mma.sync.aligned.m16n8k16.row.col.f32.bf16.bf16.f32 " \
        "{%0,%1,%2,%3},{%4,%5,%6,%7},{%8,%9},{%0,%1,%2,%3};" \
        : "+f"((c)[0]), "+f"((c)[1]), "+f"((c)[2]), "+f"((c)[3]) \
        : "r"((a)[0]), "r"((a)[1]), "r"((a)[2]), "r"((a)[3]), "r"((b)[0]), "r"((b)[1]))

static __device__ __forceinline__ uint32_t pack_bf2(__nv_bfloat16 a, __nv_bfloat16 b) {
    return (uint32_t)__bfloat16_as_ushort(a) | ((uint32_t)__bfloat16_as_ushort(b) << 16);
}

// ---------------- setup: Wc = [U1 ; U2*msg_w], c = U2*msg_b + upd_b --------
__global__ void setup_kernel(const float* __restrict__ upd_w,
                             const float* __restrict__ msg_w,
                             const float* __restrict__ upd_b,
                             const float* __restrict__ msg_b) {
    int o = blockIdx.x;
    int k = threadIdx.x;  // 256
    if (o < 256) {
        g_Wc[o * 256 + k] = upd_w[o * 512 + k];
    } else if (o < 512) {
        int oo = o - 256;
        float s = 0.f;
        #pragma unroll 8
        for (int t = 0; t < 256; ++t)
            s = fmaf(upd_w[oo * 512 + 256 + t], msg_w[t * 256 + k], s);
        g_Wc[o * 256 + k] = s;
    } else {
        float s = upd_b[k];
        for (int t = 0; t < 256; ++t)
            s = fmaf(upd_w[k * 512 + 256 + t], msg_b[t], s);
        g_c[k] = s;
    }
}

// ---------------- split fp32 -> (bf16 hi, bf16 lo) -------------------------
__global__ void split_kernel(const float* __restrict__ x, __nv_bfloat16* __restrict__ hi,
                             __nv_bfloat16* __restrict__ lo, int n4) {
    int i = blockIdx.x * blockDim.x + threadIdx.x;
    if (i >= n4) return;
    float4 v = ((const float4*)x)[i];
    __nv_bfloat16 h0 = __float2bfloat16(v.x), h1 = __float2bfloat16(v.y);
    __nv_bfloat16 h2 = __float2bfloat16(v.z), h3 = __float2bfloat16(v.w);
    uint2 ph, pl;
    ph.x = pack_bf2(h0, h1);
    ph.y = pack_bf2(h2, h3);
    pl.x = pack_bf2(__float2bfloat16(v.x - __bfloat162float(h0)),
                    __float2bfloat16(v.y - __bfloat162float(h1)));
    pl.y = pack_bf2(__float2bfloat16(v.z - __bfloat162float(h2)),
                    __float2bfloat16(v.w - __bfloat162float(h3)));
    ((uint2*)hi)[i] = ph;
    ((uint2*)lo)[i] = pl;
}

// ---------------- split-bf16 NT GEMM on mma.sync ---------------------------
// C[M,N] = (Ahi+Alo)[M,K] * (Bhi+Blo)[N,K]^T   (3 bf16 passes, fp32 regs acc)
// CTA tile 128x128, BK=32, 4 warps of 64x64, ldmatrix + cp.async double buffer.
// EPI=0: fp32 store to Cout(ldc). EPI=1: fused biases, split-bf16 -> nshi/nslo.
#define PITCH   80                    /* bytes per 32-bf16 row (16B pad) */
#define TILE_SM (128 * PITCH)         /* 10240 B */
#define STAGE_SM (4 * TILE_SM)        /* 40960 B: Ahi,Alo,Bhi,Blo */
#define SMEM_DYN (2 * STAGE_SM)       /* 81920 B */

template<int EPI>
__global__ __launch_bounds__(128, 2)
void gemm_mma(const __nv_bfloat16* __restrict__ Ahi, const __nv_bfloat16* __restrict__ Alo,
              const __nv_bfloat16* __restrict__ Bhi, const __nv_bfloat16* __restrict__ Blo,
              int K, float* __restrict__ Cout, int ldc,
              __nv_bfloat16* __restrict__ nshi, __nv_bfloat16* __restrict__ nslo,
              const float* __restrict__ colBias, const float* __restrict__ hBias,
              const float* __restrict__ hScale, const float* __restrict__ logits) {
    extern __shared__ char smem_raw[];
    const uint32_t sbase = smem_u32(smem_raw);
    const int tid = threadIdx.x;
    const int wid = tid >> 5, lane = tid & 31;
    const int m0 = blockIdx.y * 128;
    const int n0 = blockIdx.x * 128;
    const int m_w = (wid & 1) * 64;        // warp row offset in tile
    const int n_w = (wid >> 1) * 64;       // warp col offset in tile

    const __nv_bfloat16* gT[4] = { Ahi + (size_t)m0 * K, Alo + (size_t)m0 * K,
                                   Bhi + (size_t)n0 * K, Blo + (size_t)n0 * K };

    // ldmatrix lane-address components
    const int aRow  = m_w + (lane & 15);                       // + mb*16
    const int aColB = (lane >> 4) << 4;                        // 0 / 16 bytes
    const int bRow  = n_w + ((lane >> 4) << 3) + (lane & 7);   // + g*16
    const int bColB = ((lane >> 3) & 1) << 4;

    float acc[4][8][4];                                        // [mb][n8b][frag]
    #pragma unroll
    for (int a = 0; a < 4; ++a)
        #pragma unroll
        for (int b = 0; b < 8; ++b)
            #pragma unroll
            for (int c = 0; c < 4; ++c) acc[a][b][c] = 0.f;

    const int nchunk = K >> 5;

    auto load_chunk = [&](int kt, int s) {
        uint32_t st = sbase + (uint32_t)s * STAGE_SM;
        int k0 = kt * 32;
        #pragma unroll
        for (int t4 = 0; t4 < 4; ++t4) {
            const __nv_bfloat16* g = gT[t4];
            uint32_t tb = st + t4 * TILE_SM;
            #pragma unroll
            for (int i = 0; i < 4; ++i) {
                int id = tid + i * 128;
                int r = id >> 2, ch = id & 3;
                cp16(tb + (uint32_t)(r * PITCH + ch * 16), g + (size_t)r * K + k0 + ch * 8);
            }
        }
        cp_commit();
    };

    load_chunk(0, 0);
    load_chunk(1, 1);

    for (int kt = 0; kt < nchunk; ++kt) {
        const int s = kt & 1;
        if (kt + 1 < nchunk) cp_wait<1>(); else cp_wait<0>();
        __syncthreads();

        const uint32_t st  = sbase + (uint32_t)s * STAGE_SM;
        const uint32_t tAh = st;
        const uint32_t tAl = st + TILE_SM;
        const uint32_t tBh = st + 2 * TILE_SM;
        const uint32_t tBl = st + 3 * TILE_SM;

        #pragma unroll
        for (int kb = 0; kb < 2; ++kb) {
            const uint32_t aoff = (uint32_t)(kb * 32 + aColB);
            const uint32_t boff = (uint32_t)(kb * 32 + bColB);
            uint32_t ah[4][4], al[4][4], bh[4][4], bl[4][4];

            // pass 1: Ahi x Bhi
            #pragma unroll
            for (int mb = 0; mb < 4; ++mb)
                LDMX4(ah[mb][0], ah[mb][1], ah[mb][2], ah[mb][3],
                      tAh + (uint32_t)((aRow + mb * 16) * PITCH) + aoff);
            #pragma unroll
            for (int gg = 0; gg < 4; ++gg)
                LDMX4(bh[gg][0], bh[gg][1], bh[gg][2], bh[gg][3],
                      tBh + (uint32_t)((bRow + gg * 16) * PITCH) + boff);
            #pragma unroll
            for (int mb = 0; mb < 4; ++mb)
                #pragma unroll
                for (int nb = 0; nb < 8; ++nb)
                    MMA(acc[mb][nb], ah[mb], &bh[nb >> 1][(nb & 1) * 2]);

            // pass 2: Ahi x Blo
            #pragma unroll
            for (int gg = 0; gg < 4; ++gg)
                LDMX4(bl[gg][0], bl[gg][1], bl[gg][2], bl[gg][3],
                      tBl + (uint32_t)((bRow + gg * 16) * PITCH) + boff);
            #pragma unroll
            for (int mb = 0; mb < 4; ++mb)
                #pragma unroll
                for (int nb = 0; nb < 8; ++nb)
                    MMA(acc[mb][nb], ah[mb], &bl[nb >> 1][(nb & 1) * 2]);

            // pass 3: Alo x Bhi
            #pragma unroll
            for (int mb = 0; mb < 4; ++mb)
                LDMX4(al[mb][0], al[mb][1], al[mb][2], al[mb][3],
                      tAl + (uint32_t)((aRow + mb * 16) * PITCH) + aoff);
            #pragma unroll
            for (int mb = 0; mb < 4; ++mb)
                #pragma unroll
                for (int nb = 0; nb < 8; ++nb)
                    MMA(acc[mb][nb], al[mb], &bh[nb >> 1][(nb & 1) * 2]);
        }

        __syncthreads();
        if (kt + 2 < nchunk) load_chunk(kt + 2, s);
    }

    // ---- epilogue ----
    const int g  = lane >> 2;
    const int t2 = (lane & 3) * 2;
    if (EPI == 0) {
        #pragma unroll
        for (int mb = 0; mb < 4; ++mb) {
            const int r0 = m0 + m_w + mb * 16 + g;
            #pragma unroll
            for (int nb = 0; nb < 8; ++nb) {
                const int col = n0 + n_w + nb * 8 + t2;
                float2 v0 = make_float2(acc[mb][nb][0], acc[mb][nb][1]);
                float2 v1 = make_float2(acc[mb][nb][2], acc[mb][nb][3]);
                *(float2*)&Cout[(size_t)r0 * ldc + col] = v0;
                *(float2*)&Cout[(size_t)(r0 + 8) * ldc + col] = v1;
            }
        }
    } else {
        const int node = n0 >> 8;
        #pragma unroll
        for (int mb = 0; mb < 4; ++mb) {
            const int r0 = m0 + m_w + mb * 16 + g;
            const int r1 = r0 + 8;
            const float lg0 = logits[(size_t)r0 * NN + node];
            const float lg1 = logits[(size_t)r1 * NN + node];
            const size_t base0 = ((size_t)r0 * NN + node) * 256;
            const size_t base1 = ((size_t)r1 * NN + node) * 256;
            #pragma unroll
            for (int nb = 0; nb < 8; ++nb) {
                const int col = n0 + n_w + nb * 8 + t2;
                const int h = col & 255;
                const float cb0 = colBias[col] + hBias[h];
                const float cb1 = colBias[col + 1] + hBias[h + 1];
                const float s0 = hScale[h], s1 = hScale[h + 1];
                float v00 = acc[mb][nb][0] + cb0 + lg0 * s0;
                float v01 = acc[mb][nb][1] + cb1 + lg0 * s1;
                float v10 = acc[mb][nb][2] + cb0 + lg1 * s0;
                float v11 = acc[mb][nb][3] + cb1 + lg1 * s1;
                __nv_bfloat16 e00 = __float2bfloat16(v00), e01 = __float2bfloat16(v01);
                __nv_bfloat16 e10 = __float2bfloat16(v10), e11 = __float2bfloat16(v11);
                *(uint32_t*)&nshi[base0 + h] = pack_bf2(e00, e01);
                *(uint32_t*)&nslo[base0 + h] = pack_bf2(__float2bfloat16(v00 - __bfloat162float(e00)),
                                                        __float2bfloat16(v01 - __bfloat162float(e01)));
                *(uint32_t*)&nshi[base1 + h] = pack_bf2(e10, e11);
                *(uint32_t*)&nslo[base1 + h] = pack_bf2(__float2bfloat16(v10 - __bfloat162float(e10)),
                                                        __float2bfloat16(v11 - __bfloat162float(e11)));
            }
        }
    }
}

// ---------------- combine: adjacency mix + tanh -> split bf16 --------------
// Y[b,i,0:256] = ns@U1^T ; Y[b,i,256:512] = ns@(U2*msg_w)^T (=Z)
// new[b,i,h] = tanh(Y1 + sum_j A[i,j] Z[b,j,h] + c[h])
__global__ void combine_kernel(__nv_bfloat16* __restrict__ nshi,
                               __nv_bfloat16* __restrict__ nslo,
                               const float* __restrict__ Y) {
    const int b = blockIdx.x;
    const int h = threadIdx.x;  // 256
    const float* Yb = Y + (size_t)b * (NN * 512);
    float z[NN];
    float total = 0.f;
    #pragma unroll
    for (int j = 0; j < NN; ++j) { z[j] = Yb[j * 512 + 256 + h]; total += z[j]; }
    const float cb = g_c[h];
    const size_t base = (size_t)b * (NN * HID) + h;

    float pre[NN];
    pre[0] = Yb[0 * 512 + h] + total * (1.f / 9.f) + cb;
    pre[1] = Yb[1 * 512 + h] + (z[0] + z[1]) * 0.5f + cb;
    #pragma unroll
    for (int i = 2; i < 7; ++i)
        pre[i] = Yb[i * 512 + h] + (z[0] + z[i] + z[7] + z[8]) * 0.25f + cb;
    const float s78 = (total - z[1]) * 0.125f;
    pre[7] = Yb[7 * 512 + h] + s78 + cb;
    pre[8] = Yb[8 * 512 + h] + s78 + cb;
    #pragma unroll
    for (int i = 0; i < NN; ++i) {
        float t = tanhf(pre[i]);
        __nv_bfloat16 e = __float2bfloat16(t);
        nshi[base + i * 256] = e;
        nslo[base + i * 256] = __float2bfloat16(t - __bfloat162float(e));
    }
}

// ---------------- last step: nodes 7/8 combine + output dot ----------------
__global__ void final_kernel(const float* __restrict__ Y,
                             const float* __restrict__ out_w,
                             const float* __restrict__ out_b,
                             float* __restrict__ out) {
    const int b = blockIdx.x;
    const int lane = threadIdx.x & 31;
    const int node = 7 + (threadIdx.x >> 5);  // warp0 -> node7 (chronic), warp1 -> node8
    const float* Yb = Y + (size_t)b * (NN * 512);
    float acc = 0.f;
    #pragma unroll
    for (int hh = 0; hh < 8; ++hh) {
        int h = lane + hh * 32;
        float total = 0.f, z1 = 0.f;
        #pragma unroll
        for (int j = 0; j < NN; ++j) {
            float zj = Yb[j * 512 + 256 + h];
            total += zj;
            if (j == 1) z1 = zj;
        }
        float pre = Yb[node * 512 + h] + (total - z1) * 0.125f + g_c[h];
        acc += tanhf(pre) * out_w[h];
    }
    #pragma unroll
    for (int o = 16; o > 0; o >>= 1) acc += __shfl_down_sync(0xffffffffu, acc, o);
    if (lane == 0) out[(node - 7) * B_SZ + b] = acc + out_b[0];
}

// ---------------- launch ---------------------------------------------------
extern "C" void kernel_launch(void* const* d_in, const int* in_sizes, int n_in,
                              void* d_out, int out_size) {
    const float* conc   = (const float*)d_in[0];   // [B, 2048]
    const float* logits = (const float*)d_in[1];   // [B, 9]
    const float* enc_w  = (const float*)d_in[2];   // [256, 1]
    const float* enc_b  = (const float*)d_in[3];   // [256]
    const float* f2n_w  = (const float*)d_in[4];   // [2304, 2048]
    const float* f2n_b  = (const float*)d_in[5];   // [2304]
    const float* msg_w  = (const float*)d_in[6];   // [256, 256]
    const float* msg_b  = (const float*)d_in[7];   // [256]
    const float* upd_w  = (const float*)d_in[8];   // [256, 512]
    const float* upd_b  = (const float*)d_in[9];   // [256]
    const float* out_w  = (const float*)d_in[10];  // [1, 256]
    const float* out_b  = (const float*)d_in[11];  // [1]
    float* out = (float*)d_out;

    __nv_bfloat16 *Xhi, *Xlo, *nshi, *nslo, *W1hi, *W1lo, *W2hi, *W2lo;
    float *Y, *Wc;
    cudaGetSymbolAddress((void**)&Xhi,  g_Xhi);
    cudaGetSymbolAddress((void**)&Xlo,  g_Xlo);
    cudaGetSymbolAddress((void**)&nshi, g_nshi);
    cudaGetSymbolAddress((void**)&nslo, g_nslo);
    cudaGetSymbolAddress((void**)&W1hi, g_W1hi);
    cudaGetSymbolAddress((void**)&W1lo, g_W1lo);
    cudaGetSymbolAddress((void**)&W2hi, g_W2hi);
    cudaGetSymbolAddress((void**)&W2lo, g_W2lo);
    cudaGetSymbolAddress((void**)&Y,    g_Y);
    cudaGetSymbolAddress((void**)&Wc,   g_Wc);

    cudaFuncSetAttribute((const void*)gemm_mma<0>, cudaFuncAttributeMaxDynamicSharedMemorySize, SMEM_DYN);
    cudaFuncSetAttribute((const void*)gemm_mma<1>, cudaFuncAttributeMaxDynamicSharedMemorySize, SMEM_DYN);

    // fold weights, then split everything to bf16 hi/lo
    setup_kernel<<<513, 256>>>(upd_w, msg_w, upd_b, msg_b);
    int n4 = (B_SZ * FDIM) / 4;
    split_kernel<<<(n4 + 255) / 256, 256>>>(conc, Xhi, Xlo, n4);
    n4 = (NN * HID * FDIM) / 4;
    split_kernel<<<(n4 + 255) / 256, 256>>>(f2n_w, W1hi, W1lo, n4);
    n4 = (512 * 256) / 4;
    split_kernel<<<(n4 + 255) / 256, 256>>>(Wc, W2hi, W2lo, n4);

    // ns = conc @ f2n_w^T + biases  -> split-bf16 node states [B*9, 256]
    gemm_mma<1><<<dim3((NN * HID) / 128, B_SZ / 128), 128, SMEM_DYN>>>(
        Xhi, Xlo, W1hi, W1lo, FDIM, nullptr, 0,
        nshi, nslo, f2n_b, enc_b, enc_w, logits);

    for (int s = 0; s < 4; ++s) {
        // Y = ns @ Wc^T : [B*9, 256] x [512, 256]^T -> [B*9, 512] fp32
        gemm_mma<0><<<dim3(512 / 128, BROWS / 128), 128, SMEM_DYN>>>(
            nshi, nslo, W2hi, W2lo, HID, Y, 512,
            nullptr, nullptr, nullptr, nullptr, nullptr, nullptr);
        if (s < 3)
            combine_kernel<<<B_SZ, 256>>>(nshi, nslo, Y);
        else
            final_kernel<<<B_SZ, 64>>>(Y, out_w, out_b, out);
    }
}

// round 9
// speedup vs baseline: 1.6707x; 1.3232x over previous
#include <cuda_runtime.h>
#include <cuda_fp16.h>
#include <cstdint>

#define B_SZ 16384
#define FDIM 2048
#define HID  256
#define NN   9
#define BROWS (B_SZ * NN)   /* 147456 */

// ---------------- scratch (static device globals; no allocations) ----------
__device__ __align__(256) __half g_X[(size_t)B_SZ * FDIM];                 // conc fp16
__device__ __align__(256) __half g_ns[(size_t)BROWS * HID];                // node states fp16
__device__ __align__(256) __half g_W1hi[(size_t)(NN * HID) * FDIM];        // f2n_w hi
__device__ __align__(256) __half g_W1lo[(size_t)(NN * HID) * FDIM];        // f2n_w lo
__device__ __align__(256) __half g_W2hi[512 * 256];                        // Wc hi
__device__ __align__(256) __half g_W2lo[512 * 256];                        // Wc lo
__device__ __align__(256) float g_Y[(size_t)BROWS * 512];                  // step GEMM out
__device__ __align__(256) float g_Wc[512 * 256];                           // [U1 ; U2*msg_w]
__device__ float g_c[256];                                                 // U2*msg_b + upd_b

// ---------------- PTX helpers (baseline sm_80/sm_100 features only) --------
static __device__ __forceinline__ uint32_t smem_u32(const void* p) {
    uint32_t a;
    asm("{ .reg .u64 t; cvta.to.shared.u64 t, %1; cvt.u32.u64 %0, t; }" : "=r"(a) : "l"(p));
    return a;
}
static __device__ __forceinline__ void cp16(uint32_t s, const void* g) {
    asm volatile("cp.async.cg.shared.global [%0], [%1], 16;" :: "r"(s), "l"(g));
}
static __device__ __forceinline__ void cp_commit() { asm volatile("cp.async.commit_group;"); }
template<int N> static __device__ __forceinline__ void cp_wait() {
    asm volatile("cp.async.wait_group %0;" :: "n"(N));
}
#define LDMX4(r0, r1, r2, r3, a) \
    asm volatile("ldmatrix.sync.aligned.m8n8.x4.shared.b16 {%0,%1,%2,%3}, [%4];" \
        : "=r"(r0), "=r"(r1), "=r"(r2), "=r"(r3) : "r"(a))
#define MMA(c, a, b) \
    asm volatile("mma.sync.aligned.m16n8k16.row.col.f32.f16.f16.f32 " \
        "{%0,%1,%2,%3},{%4,%5,%6,%7},{%8,%9},{%0,%1,%2,%3};" \
        : "+f"((c)[0]), "+f"((c)[1]), "+f"((c)[2]), "+f"((c)[3]) \
        : "r"((a)[0]), "r"((a)[1]), "r"((a)[2]), "r"((a)[3]), "r"((b)[0]), "r"((b)[1]))

static __device__ __forceinline__ uint32_t pack_h2(__half a, __half b) {
    return (uint32_t)__half_as_ushort(a) | ((uint32_t)__half_as_ushort(b) << 16);
}

// ---------------- setup: Wc = [U1 ; U2*msg_w], c = U2*msg_b + upd_b --------
__global__ void setup_kernel(const float* __restrict__ upd_w,
                             const float* __restrict__ msg_w,
                             const float* __restrict__ upd_b,
                             const float* __restrict__ msg_b) {
    int o = blockIdx.x;
    int k = threadIdx.x;  // 256
    if (o < 256) {
        g_Wc[o * 256 + k] = upd_w[o * 512 + k];
    } else if (o < 512) {
        int oo = o - 256;
        float s = 0.f;
        #pragma unroll 8
        for (int t = 0; t < 256; ++t)
            s = fmaf(upd_w[oo * 512 + 256 + t], msg_w[t * 256 + k], s);
        g_Wc[o * 256 + k] = s;
    } else {
        float s = upd_b[k];
        for (int t = 0; t < 256; ++t)
            s = fmaf(upd_w[k * 512 + 256 + t], msg_b[t], s);
        g_c[k] = s;
    }
}

// ---------------- fp32 -> fp16 (single) ------------------------------------
__global__ void tohalf_kernel(const float* __restrict__ x, __half* __restrict__ o, int n4) {
    int i = blockIdx.x * blockDim.x + threadIdx.x;
    if (i >= n4) return;
    float4 v = ((const float4*)x)[i];
    uint2 p;
    p.x = pack_h2(__float2half(v.x), __float2half(v.y));
    p.y = pack_h2(__float2half(v.z), __float2half(v.w));
    ((uint2*)o)[i] = p;
}

// ---------------- fp32 -> (fp16 hi, fp16 lo) -------------------------------
__global__ void splithalf_kernel(const float* __restrict__ x, __half* __restrict__ hi,
                                 __half* __restrict__ lo, int n4) {
    int i = blockIdx.x * blockDim.x + threadIdx.x;
    if (i >= n4) return;
    float4 v = ((const float4*)x)[i];
    __half h0 = __float2half(v.x), h1 = __float2half(v.y);
    __half h2 = __float2half(v.z), h3 = __float2half(v.w);
    uint2 ph, pl;
    ph.x = pack_h2(h0, h1);
    ph.y = pack_h2(h2, h3);
    pl.x = pack_h2(__float2half(v.x - __half2float(h0)),
                   __float2half(v.y - __half2float(h1)));
    pl.y = pack_h2(__float2half(v.z - __half2float(h2)),
                   __float2half(v.w - __half2float(h3)));
    ((uint2*)hi)[i] = ph;
    ((uint2*)lo)[i] = pl;
}

// ---------------- fp16 2-pass NT GEMM on mma.sync --------------------------
// C[M,N] = A[M,K] * (Bhi+Blo)[N,K]^T   (A single fp16; 2 passes, fp32 acc)
// CTA tile 128x128, BK=32, 4 warps of 64x64, ldmatrix + cp.async double buffer.
// EPI=0: fp32 store to Cout(ldc). EPI=1: fused biases -> fp16 ns.
#define PITCH   80                    /* bytes per 32-half row (16B pad) */
#define TILE_SM (128 * PITCH)         /* 10240 B */
#define STAGE_SM (3 * TILE_SM)        /* 30720 B: A, Bhi, Blo */
#define SMEM_DYN (2 * STAGE_SM)       /* 61440 B */

template<int EPI>
__global__ __launch_bounds__(128, 2)
void gemm_mma(const __half* __restrict__ A,
              const __half* __restrict__ Bhi, const __half* __restrict__ Blo,
              int K, float* __restrict__ Cout, int ldc,
              __half* __restrict__ ns,
              const float* __restrict__ colBias, const float* __restrict__ hBias,
              const float* __restrict__ hScale, const float* __restrict__ logits) {
    extern __shared__ char smem_raw[];
    const uint32_t sbase = smem_u32(smem_raw);
    const int tid = threadIdx.x;
    const int wid = tid >> 5, lane = tid & 31;
    const int m0 = blockIdx.y * 128;
    const int n0 = blockIdx.x * 128;
    const int m_w = (wid & 1) * 64;        // warp row offset in tile
    const int n_w = (wid >> 1) * 64;       // warp col offset in tile

    const __half* gT[3] = { A + (size_t)m0 * K, Bhi + (size_t)n0 * K, Blo + (size_t)n0 * K };

    // ldmatrix lane-address components
    const int aRow  = m_w + (lane & 15);                       // + mb*16
    const int aColB = (lane >> 4) << 4;                        // 0 / 16 bytes
    const int bRow  = n_w + ((lane >> 4) << 3) + (lane & 7);   // + g*16
    const int bColB = ((lane >> 3) & 1) << 4;

    float acc[4][8][4];                                        // [mb][n8b][frag]
    #pragma unroll
    for (int a = 0; a < 4; ++a)
        #pragma unroll
        for (int b = 0; b < 8; ++b)
            #pragma unroll
            for (int c = 0; c < 4; ++c) acc[a][b][c] = 0.f;

    const int nchunk = K >> 5;

    auto load_chunk = [&](int kt, int s) {
        uint32_t st = sbase + (uint32_t)s * STAGE_SM;
        int k0 = kt * 32;
        #pragma unroll
        for (int t3 = 0; t3 < 3; ++t3) {
            const __half* g = gT[t3];
            uint32_t tb = st + t3 * TILE_SM;
            #pragma unroll
            for (int i = 0; i < 4; ++i) {
                int id = tid + i * 128;
                int r = id >> 2, ch = id & 3;
                cp16(tb + (uint32_t)(r * PITCH + ch * 16), g + (size_t)r * K + k0 + ch * 8);
            }
        }
        cp_commit();
    };

    load_chunk(0, 0);
    load_chunk(1, 1);

    for (int kt = 0; kt < nchunk; ++kt) {
        const int s = kt & 1;
        if (kt + 1 < nchunk) cp_wait<1>(); else cp_wait<0>();
        __syncthreads();

        const uint32_t st  = sbase + (uint32_t)s * STAGE_SM;
        const uint32_t tA  = st;
        const uint32_t tBh = st + TILE_SM;
        const uint32_t tBl = st + 2 * TILE_SM;

        #pragma unroll
        for (int kb = 0; kb < 2; ++kb) {
            const uint32_t aoff = (uint32_t)(kb * 32 + aColB);
            const uint32_t boff = (uint32_t)(kb * 32 + bColB);
            uint32_t af[4][4], bh[4][4], bl[4][4];

            #pragma unroll
            for (int mb = 0; mb < 4; ++mb)
                LDMX4(af[mb][0], af[mb][1], af[mb][2], af[mb][3],
                      tA + (uint32_t)((aRow + mb * 16) * PITCH) + aoff);

            // pass 1: A x Bhi
            #pragma unroll
            for (int gg = 0; gg < 4; ++gg)
                LDMX4(bh[gg][0], bh[gg][1], bh[gg][2], bh[gg][3],
                      tBh + (uint32_t)((bRow + gg * 16) * PITCH) + boff);
            #pragma unroll
            for (int mb = 0; mb < 4; ++mb)
                #pragma unroll
                for (int nb = 0; nb < 8; ++nb)
                    MMA(acc[mb][nb], af[mb], &bh[nb >> 1][(nb & 1) * 2]);

            // pass 2: A x Blo
            #pragma unroll
            for (int gg = 0; gg < 4; ++gg)
                LDMX4(bl[gg][0], bl[gg][1], bl[gg][2], bl[gg][3],
                      tBl + (uint32_t)((bRow + gg * 16) * PITCH) + boff);
            #pragma unroll
            for (int mb = 0; mb < 4; ++mb)
                #pragma unroll
                for (int nb = 0; nb < 8; ++nb)
                    MMA(acc[mb][nb], af[mb], &bl[nb >> 1][(nb & 1) * 2]);
        }

        __syncthreads();
        if (kt + 2 < nchunk) load_chunk(kt + 2, s);
    }

    // ---- epilogue ----
    const int g  = lane >> 2;
    const int t2 = (lane & 3) * 2;
    if (EPI == 0) {
        #pragma unroll
        for (int mb = 0; mb < 4; ++mb) {
            const int r0 = m0 + m_w + mb * 16 + g;
            #pragma unroll
            for (int nb = 0; nb < 8; ++nb) {
                const int col = n0 + n_w + nb * 8 + t2;
                float2 v0 = make_float2(acc[mb][nb][0], acc[mb][nb][1]);
                float2 v1 = make_float2(acc[mb][nb][2], acc[mb][nb][3]);
                *(float2*)&Cout[(size_t)r0 * ldc + col] = v0;
                *(float2*)&Cout[(size_t)(r0 + 8) * ldc + col] = v1;
            }
        }
    } else {
        const int node = n0 >> 8;
        #pragma unroll
        for (int mb = 0; mb < 4; ++mb) {
            const int r0 = m0 + m_w + mb * 16 + g;
            const int r1 = r0 + 8;
            const float lg0 = logits[(size_t)r0 * NN + node];
            const float lg1 = logits[(size_t)r1 * NN + node];
            const size_t base0 = ((size_t)r0 * NN + node) * 256;
            const size_t base1 = ((size_t)r1 * NN + node) * 256;
            #pragma unroll
            for (int nb = 0; nb < 8; ++nb) {
                const int col = n0 + n_w + nb * 8 + t2;
                const int h = col & 255;
                const float cb0 = colBias[col] + hBias[h];
                const float cb1 = colBias[col + 1] + hBias[h + 1];
                const float s0 = hScale[h], s1 = hScale[h + 1];
                float v00 = acc[mb][nb][0] + cb0 + lg0 * s0;
                float v01 = acc[mb][nb][1] + cb1 + lg0 * s1;
                float v10 = acc[mb][nb][2] + cb0 + lg1 * s0;
                float v11 = acc[mb][nb][3] + cb1 + lg1 * s1;
                *(uint32_t*)&ns[base0 + h] = pack_h2(__float2half(v00), __float2half(v01));
                *(uint32_t*)&ns[base1 + h] = pack_h2(__float2half(v10), __float2half(v11));
            }
        }
    }
}

// ---------------- combine: adjacency mix + tanh -> fp16 ns -----------------
// Y[b,i,0:256] = ns@U1^T ; Y[b,i,256:512] = ns@(U2*msg_w)^T (=Z)
// new[b,i,h] = tanh(Y1 + sum_j A[i,j] Z[b,j,h] + c[h])
__global__ void combine_kernel(__half* __restrict__ ns, const float* __restrict__ Y) {
    const int b = blockIdx.x;
    const int h = threadIdx.x;  // 256
    const float* Yb = Y + (size_t)b * (NN * 512);
    float z[NN];
    float total = 0.f;
    #pragma unroll
    for (int j = 0; j < NN; ++j) { z[j] = Yb[j * 512 + 256 + h]; total += z[j]; }
    const float cb = g_c[h];
    const size_t base = (size_t)b * (NN * HID) + h;

    float pre[NN];
    pre[0] = Yb[0 * 512 + h] + total * (1.f / 9.f) + cb;
    pre[1] = Yb[1 * 512 + h] + (z[0] + z[1]) * 0.5f + cb;
    #pragma unroll
    for (int i = 2; i < 7; ++i)
        pre[i] = Yb[i * 512 + h] + (z[0] + z[i] + z[7] + z[8]) * 0.25f + cb;
    const float s78 = (total - z[1]) * 0.125f;
    pre[7] = Yb[7 * 512 + h] + s78 + cb;
    pre[8] = Yb[8 * 512 + h] + s78 + cb;
    #pragma unroll
    for (int i = 0; i < NN; ++i)
        ns[base + i * 256] = __float2half(tanhf(pre[i]));
}

// ---------------- last step: nodes 7/8 combine + output dot ----------------
__global__ void final_kernel(const float* __restrict__ Y,
                             const float* __restrict__ out_w,
                             const float* __restrict__ out_b,
                             float* __restrict__ out) {
    const int b = blockIdx.x;
    const int lane = threadIdx.x & 31;
    const int node = 7 + (threadIdx.x >> 5);  // warp0 -> node7 (chronic), warp1 -> node8
    const float* Yb = Y + (size_t)b * (NN * 512);
    float acc = 0.f;
    #pragma unroll
    for (int hh = 0; hh < 8; ++hh) {
        int h = lane + hh * 32;
        float total = 0.f, z1 = 0.f;
        #pragma unroll
        for (int j = 0; j < NN; ++j) {
            float zj = Yb[j * 512 + 256 + h];
            total += zj;
            if (j == 1) z1 = zj;
        }
        float pre = Yb[node * 512 + h] + (total - z1) * 0.125f + g_c[h];
        acc += tanhf(pre) * out_w[h];
    }
    #pragma unroll
    for (int o = 16; o > 0; o >>= 1) acc += __shfl_down_sync(0xffffffffu, acc, o);
    if (lane == 0) out[(node - 7) * B_SZ + b] = acc + out_b[0];
}

// ---------------- launch ---------------------------------------------------
extern "C" void kernel_launch(void* const* d_in, const int* in_sizes, int n_in,
                              void* d_out, int out_size) {
    const float* conc   = (const float*)d_in[0];   // [B, 2048]
    const float* logits = (const float*)d_in[1];   // [B, 9]
    const float* enc_w  = (const float*)d_in[2];   // [256, 1]
    const float* enc_b  = (const float*)d_in[3];   // [256]
    const float* f2n_w  = (const float*)d_in[4];   // [2304, 2048]
    const float* f2n_b  = (const float*)d_in[5];   // [2304]
    const float* msg_w  = (const float*)d_in[6];   // [256, 256]
    const float* msg_b  = (const float*)d_in[7];   // [256]
    const float* upd_w  = (const float*)d_in[8];   // [256, 512]
    const float* upd_b  = (const float*)d_in[9];   // [256]
    const float* out_w  = (const float*)d_in[10];  // [1, 256]
    const float* out_b  = (const float*)d_in[11];  // [1]
    float* out = (float*)d_out;

    __half *X, *ns, *W1hi, *W1lo, *W2hi, *W2lo;
    float *Y, *Wc;
    cudaGetSymbolAddress((void**)&X,    g_X);
    cudaGetSymbolAddress((void**)&ns,   g_ns);
    cudaGetSymbolAddress((void**)&W1hi, g_W1hi);
    cudaGetSymbolAddress((void**)&W1lo, g_W1lo);
    cudaGetSymbolAddress((void**)&W2hi, g_W2hi);
    cudaGetSymbolAddress((void**)&W2lo, g_W2lo);
    cudaGetSymbolAddress((void**)&Y,    g_Y);
    cudaGetSymbolAddress((void**)&Wc,   g_Wc);

    cudaFuncSetAttribute((const void*)gemm_mma<0>, cudaFuncAttributeMaxDynamicSharedMemorySize, SMEM_DYN);
    cudaFuncSetAttribute((const void*)gemm_mma<1>, cudaFuncAttributeMaxDynamicSharedMemorySize, SMEM_DYN);

    // fold weights; convert conc to fp16; split weights to fp16 hi/lo
    setup_kernel<<<513, 256>>>(upd_w, msg_w, upd_b, msg_b);
    int n4 = (B_SZ * FDIM) / 4;
    tohalf_kernel<<<(n4 + 255) / 256, 256>>>(conc, X, n4);
    n4 = (NN * HID * FDIM) / 4;
    splithalf_kernel<<<(n4 + 255) / 256, 256>>>(f2n_w, W1hi, W1lo, n4);
    n4 = (512 * 256) / 4;
    splithalf_kernel<<<(n4 + 255) / 256, 256>>>(Wc, W2hi, W2lo, n4);

    // ns = conc @ f2n_w^T + biases  -> fp16 node states [B*9, 256]
    gemm_mma<1><<<dim3((NN * HID) / 128, B_SZ / 128), 128, SMEM_DYN>>>(
        X, W1hi, W1lo, FDIM, nullptr, 0,
        ns, f2n_b, enc_b, enc_w, logits);

    for (int s = 0; s < 4; ++s) {
        // Y = ns @ Wc^T : [B*9, 256] x [512, 256]^T -> [B*9, 512] fp32
        gemm_mma<0><<<dim3(512 / 128, BROWS / 128), 128, SMEM_DYN>>>(
            ns, W2hi, W2lo, HID, Y, 512,
            nullptr, nullptr, nullptr, nullptr, nullptr);
        if (s < 3)
            combine_kernel<<<B_SZ, 256>>>(ns, Y);
        else
            final_kernel<<<B_SZ, 64>>>(Y, out_w, out_b, out);
    }
}

// round 11
// speedup vs baseline: 2.7905x; 1.6703x over previous
#include <cuda_runtime.h>
#include <cuda_fp16.h>
#include <cstdint>

#define B_SZ 16384
#define FDIM 2048
#define HID  256
#define NN   9
#define BROWS (B_SZ * NN)   /* 147456 */

// ---------------- scratch (static device globals; no allocations) ----------
__device__ __align__(256) __half g_X[(size_t)B_SZ * FDIM];                 // conc fp16
__device__ __align__(256) __half g_ns[(size_t)BROWS * HID];                // node states fp16
__device__ __align__(256) __half g_W1[(size_t)(NN * HID) * FDIM];          // f2n_w fp16
__device__ __align__(256) __half g_W2[512 * 256];                          // Wc fp16
__device__ __align__(256) __half g_Y[(size_t)BROWS * 512];                 // step GEMM out (fp16)
__device__ __align__(256) float g_Wc[512 * 256];                           // [U1 ; U2*msg_w]
__device__ float g_c[256];                                                 // U2*msg_b + upd_b

// ---------------- PTX helpers (baseline sm_80/sm_100 features only) --------
static __device__ __forceinline__ uint32_t smem_u32(const void* p) {
    uint32_t a;
    asm("{ .reg .u64 t; cvta.to.shared.u64 t, %1; cvt.u32.u64 %0, t; }" : "=r"(a) : "l"(p));
    return a;
}
static __device__ __forceinline__ void cp16(uint32_t s, const void* g) {
    asm volatile("cp.async.cg.shared.global [%0], [%1], 16;" :: "r"(s), "l"(g));
}
static __device__ __forceinline__ void cp_commit() { asm volatile("cp.async.commit_group;"); }
template<int N> static __device__ __forceinline__ void cp_wait() {
    asm volatile("cp.async.wait_group %0;" :: "n"(N));
}
#define LDMX4(r0, r1, r2, r3, a) \
    asm volatile("ldmatrix.sync.aligned.m8n8.x4.shared.b16 {%0,%1,%2,%3}, [%4];" \
        : "=r"(r0), "=r"(r1), "=r"(r2), "=r"(r3) : "r"(a))
#define MMA(c, a, b) \
    asm volatile("mma.sync.aligned.m16n8k16.row.col.f32.f16.f16.f32 " \
        "{%0,%1,%2,%3},{%4,%5,%6,%7},{%8,%9},{%0,%1,%2,%3};" \
        : "+f"((c)[0]), "+f"((c)[1]), "+f"((c)[2]), "+f"((c)[3]) \
        : "r"((a)[0]), "r"((a)[1]), "r"((a)[2]), "r"((a)[3]), "r"((b)[0]), "r"((b)[1]))

static __device__ __forceinline__ uint32_t pack_h2(__half a, __half b) {
    return (uint32_t)__half_as_ushort(a) | ((uint32_t)__half_as_ushort(b) << 16);
}

// ---------------- setup: Wc = [U1 ; U2*msg_w], c = U2*msg_b + upd_b --------
__global__ void setup_kernel(const float* __restrict__ upd_w,
                             const float* __restrict__ msg_w,
                             const float* __restrict__ upd_b,
                             const float* __restrict__ msg_b) {
    int o = blockIdx.x;
    int k = threadIdx.x;  // 256
    if (o < 256) {
        g_Wc[o * 256 + k] = upd_w[o * 512 + k];
    } else if (o < 512) {
        int oo = o - 256;
        float s = 0.f;
        #pragma unroll 8
        for (int t = 0; t < 256; ++t)
            s = fmaf(upd_w[oo * 512 + 256 + t], msg_w[t * 256 + k], s);
        g_Wc[o * 256 + k] = s;
    } else {
        float s = upd_b[k];
        for (int t = 0; t < 256; ++t)
            s = fmaf(upd_w[k * 512 + 256 + t], msg_b[t], s);
        g_c[k] = s;
    }
}

// ---------------- fp32 -> fp16 ---------------------------------------------
__global__ void tohalf_kernel(const float* __restrict__ x, __half* __restrict__ o, int n4) {
    int i = blockIdx.x * blockDim.x + threadIdx.x;
    if (i >= n4) return;
    float4 v = ((const float4*)x)[i];
    uint2 p;
    p.x = pack_h2(__float2half(v.x), __float2half(v.y));
    p.y = pack_h2(__float2half(v.z), __float2half(v.w));
    ((uint2*)o)[i] = p;
}

// ---------------- fp16 NT GEMM on mma.sync ---------------------------------
// C[M,N] = A[M,K] * B[N,K]^T   (fp16 in, fp32 acc)
// CTA tile 128x128, BK=32, 4 warps of 64x64, ldmatrix + cp.async double buffer.
// EPI=0: fp16 store to Yout(ldc). EPI=1: fused biases -> fp16 ns.
#define PITCH   80                    /* bytes per 32-half row (16B pad) */
#define TILE_SM (128 * PITCH)         /* 10240 B */
#define STAGE_SM (2 * TILE_SM)        /* 20480 B: A, B */
#define SMEM_DYN (2 * STAGE_SM)       /* 40960 B */

template<int EPI>
__global__ __launch_bounds__(128, 2)
void gemm_mma(const __half* __restrict__ A, const __half* __restrict__ B,
              int K, __half* __restrict__ Yout, int ldc,
              __half* __restrict__ ns,
              const float* __restrict__ colBias, const float* __restrict__ hBias,
              const float* __restrict__ hScale, const float* __restrict__ logits) {
    extern __shared__ char smem_raw[];
    const uint32_t sbase = smem_u32(smem_raw);
    const int tid = threadIdx.x;
    const int wid = tid >> 5, lane = tid & 31;
    const int m0 = blockIdx.y * 128;
    const int n0 = blockIdx.x * 128;
    const int m_w = (wid & 1) * 64;        // warp row offset in tile
    const int n_w = (wid >> 1) * 64;       // warp col offset in tile

    const __half* gA = A + (size_t)m0 * K;
    const __half* gB = B + (size_t)n0 * K;

    // ldmatrix lane-address components
    const int aRow  = m_w + (lane & 15);                       // + mb*16
    const int aColB = (lane >> 4) << 4;                        // 0 / 16 bytes
    const int bRow  = n_w + ((lane >> 4) << 3) + (lane & 7);   // + g*16
    const int bColB = ((lane >> 3) & 1) << 4;

    float acc[4][8][4];                                        // [mb][n8b][frag]
    #pragma unroll
    for (int a = 0; a < 4; ++a)
        #pragma unroll
        for (int b = 0; b < 8; ++b)
            #pragma unroll
            for (int c = 0; c < 4; ++c) acc[a][b][c] = 0.f;

    const int nchunk = K >> 5;

    auto load_chunk = [&](int kt, int s) {
        uint32_t st = sbase + (uint32_t)s * STAGE_SM;
        int k0 = kt * 32;
        #pragma unroll
        for (int i = 0; i < 4; ++i) {
            int id = tid + i * 128;
            int r = id >> 2, ch = id & 3;
            cp16(st + (uint32_t)(r * PITCH + ch * 16), gA + (size_t)r * K + k0 + ch * 8);
            cp16(st + TILE_SM + (uint32_t)(r * PITCH + ch * 16), gB + (size_t)r * K + k0 + ch * 8);
        }
        cp_commit();
    };

    load_chunk(0, 0);
    load_chunk(1, 1);

    for (int kt = 0; kt < nchunk; ++kt) {
        const int s = kt & 1;
        if (kt + 1 < nchunk) cp_wait<1>(); else cp_wait<0>();
        __syncthreads();

        const uint32_t tA = sbase + (uint32_t)s * STAGE_SM;
        const uint32_t tB = tA + TILE_SM;

        #pragma unroll
        for (int kb = 0; kb < 2; ++kb) {
            const uint32_t aoff = (uint32_t)(kb * 32 + aColB);
            const uint32_t boff = (uint32_t)(kb * 32 + bColB);
            uint32_t af[4][4], bf[4][4];

            #pragma unroll
            for (int mb = 0; mb < 4; ++mb)
                LDMX4(af[mb][0], af[mb][1], af[mb][2], af[mb][3],
                      tA + (uint32_t)((aRow + mb * 16) * PITCH) + aoff);
            #pragma unroll
            for (int gg = 0; gg < 4; ++gg)
                LDMX4(bf[gg][0], bf[gg][1], bf[gg][2], bf[gg][3],
                      tB + (uint32_t)((bRow + gg * 16) * PITCH) + boff);
            #pragma unroll
            for (int mb = 0; mb < 4; ++mb)
                #pragma unroll
                for (int nb = 0; nb < 8; ++nb)
                    MMA(acc[mb][nb], af[mb], &bf[nb >> 1][(nb & 1) * 2]);
        }

        __syncthreads();
        if (kt + 2 < nchunk) load_chunk(kt + 2, s);
    }

    // ---- epilogue ----
    const int g  = lane >> 2;
    const int t2 = (lane & 3) * 2;
    if (EPI == 0) {
        #pragma unroll
        for (int mb = 0; mb < 4; ++mb) {
            const int r0 = m0 + m_w + mb * 16 + g;
            #pragma unroll
            for (int nb = 0; nb < 8; ++nb) {
                const int col = n0 + n_w + nb * 8 + t2;
                *(uint32_t*)&Yout[(size_t)r0 * ldc + col] =
                    pack_h2(__float2half(acc[mb][nb][0]), __float2half(acc[mb][nb][1]));
                *(uint32_t*)&Yout[(size_t)(r0 + 8) * ldc + col] =
                    pack_h2(__float2half(acc[mb][nb][2]), __float2half(acc[mb][nb][3]));
            }
        }
    } else {
        const int node = n0 >> 8;
        #pragma unroll
        for (int mb = 0; mb < 4; ++mb) {
            const int r0 = m0 + m_w + mb * 16 + g;
            const int r1 = r0 + 8;
            const float lg0 = logits[(size_t)r0 * NN + node];
            const float lg1 = logits[(size_t)r1 * NN + node];
            const size_t base0 = ((size_t)r0 * NN + node) * 256;
            const size_t base1 = ((size_t)r1 * NN + node) * 256;
            #pragma unroll
            for (int nb = 0; nb < 8; ++nb) {
                const int col = n0 + n_w + nb * 8 + t2;
                const int h = col & 255;
                const float cb0 = colBias[col] + hBias[h];
                const float cb1 = colBias[col + 1] + hBias[h + 1];
                const float s0 = hScale[h], s1 = hScale[h + 1];
                float v00 = acc[mb][nb][0] + cb0 + lg0 * s0;
                float v01 = acc[mb][nb][1] + cb1 + lg0 * s1;
                float v10 = acc[mb][nb][2] + cb0 + lg1 * s0;
                float v11 = acc[mb][nb][3] + cb1 + lg1 * s1;
                *(uint32_t*)&ns[base0 + h] = pack_h2(__float2half(v00), __float2half(v01));
                *(uint32_t*)&ns[base1 + h] = pack_h2(__float2half(v10), __float2half(v11));
            }
        }
    }
}

// ---------------- combine: adjacency mix + tanh -> fp16 ns -----------------
// Y[b,i,0:256] = ns@U1^T ; Y[b,i,256:512] = ns@(U2*msg_w)^T (=Z)
// new[b,i,h] = tanh(Y1 + sum_j A[i,j] Z[b,j,h] + c[h])
__global__ void combine_kernel(__half* __restrict__ ns, const __half* __restrict__ Y) {
    const int b = blockIdx.x;
    const int h = threadIdx.x;  // 256
    const __half* Yb = Y + (size_t)b * (NN * 512);
    float z[NN];
    float total = 0.f;
    #pragma unroll
    for (int j = 0; j < NN; ++j) { z[j] = __half2float(Yb[j * 512 + 256 + h]); total += z[j]; }
    const float cb = g_c[h];
    const size_t base = (size_t)b * (NN * HID) + h;

    float pre[NN];
    pre[0] = __half2float(Yb[0 * 512 + h]) + total * (1.f / 9.f) + cb;
    pre[1] = __half2float(Yb[1 * 512 + h]) + (z[0] + z[1]) * 0.5f + cb;
    #pragma unroll
    for (int i = 2; i < 7; ++i)
        pre[i] = __half2float(Yb[i * 512 + h]) + (z[0] + z[i] + z[7] + z[8]) * 0.25f + cb;
    const float s78 = (total - z[1]) * 0.125f;
    pre[7] = __half2float(Yb[7 * 512 + h]) + s78 + cb;
    pre[8] = __half2float(Yb[8 * 512 + h]) + s78 + cb;
    #pragma unroll
    for (int i = 0; i < NN; ++i)
        ns[base + i * 256] = __float2half(tanhf(pre[i]));
}

// ---------------- last step: nodes 7/8 combine + output dot ----------------
__global__ void final_kernel(const __half* __restrict__ Y,
                             const float* __restrict__ out_w,
                             const float* __restrict__ out_b,
                             float* __restrict__ out) {
    const int b = blockIdx.x;
    const int lane = threadIdx.x & 31;
    const int node = 7 + (threadIdx.x >> 5);  // warp0 -> node7 (chronic), warp1 -> node8
    const __half* Yb = Y + (size_t)b * (NN * 512);
    float acc = 0.f;
    #pragma unroll
    for (int hh = 0; hh < 8; ++hh) {
        int h = lane + hh * 32;
        float total = 0.f, z1 = 0.f;
        #pragma unroll
        for (int j = 0; j < NN; ++j) {
            float zj = __half2float(Yb[j * 512 + 256 + h]);
            total += zj;
            if (j == 1) z1 = zj;
        }
        float pre = __half2float(Yb[node * 512 + h]) + (total - z1) * 0.125f + g_c[h];
        acc += tanhf(pre) * out_w[h];
    }
    #pragma unroll
    for (int o = 16; o > 0; o >>= 1) acc += __shfl_down_sync(0xffffffffu, acc, o);
    if (lane == 0) out[(node - 7) * B_SZ + b] = acc + out_b[0];
}

// ---------------- launch ---------------------------------------------------
extern "C" void kernel_launch(void* const* d_in, const int* in_sizes, int n_in,
                              void* d_out, int out_size) {
    const float* conc   = (const float*)d_in[0];   // [B, 2048]
    const float* logits = (const float*)d_in[1];   // [B, 9]
    const float* enc_w  = (const float*)d_in[2];   // [256, 1]
    const float* enc_b  = (const float*)d_in[3];   // [256]
    const float* f2n_w  = (const float*)d_in[4];   // [2304, 2048]
    const float* f2n_b  = (const float*)d_in[5];   // [2304]
    const float* msg_w  = (const float*)d_in[6];   // [256, 256]
    const float* msg_b  = (const float*)d_in[7];   // [256]
    const float* upd_w  = (const float*)d_in[8];   // [256, 512]
    const float* upd_b  = (const float*)d_in[9];   // [256]
    const float* out_w  = (const float*)d_in[10];  // [1, 256]
    const float* out_b  = (const float*)d_in[11];  // [1]
    float* out = (float*)d_out;

    __half *X, *ns, *W1, *W2, *Y;
    float *Wc;
    cudaGetSymbolAddress((void**)&X,  g_X);
    cudaGetSymbolAddress((void**)&ns, g_ns);
    cudaGetSymbolAddress((void**)&W1, g_W1);
    cudaGetSymbolAddress((void**)&W2, g_W2);
    cudaGetSymbolAddress((void**)&Y,  g_Y);
    cudaGetSymbolAddress((void**)&Wc, g_Wc);

    cudaFuncSetAttribute((const void*)gemm_mma<0>, cudaFuncAttributeMaxDynamicSharedMemorySize, SMEM_DYN);
    cudaFuncSetAttribute((const void*)gemm_mma<1>, cudaFuncAttributeMaxDynamicSharedMemorySize, SMEM_DYN);

    // fold weights; convert everything to fp16
    setup_kernel<<<513, 256>>>(upd_w, msg_w, upd_b, msg_b);
    int n4 = (B_SZ * FDIM) / 4;
    tohalf_kernel<<<(n4 + 255) / 256, 256>>>(conc, X, n4);
    n4 = (NN * HID * FDIM) / 4;
    tohalf_kernel<<<(n4 + 255) / 256, 256>>>(f2n_w, W1, n4);
    n4 = (512 * 256) / 4;
    tohalf_kernel<<<(n4 + 255) / 256, 256>>>(Wc, W2, n4);

    // ns = conc @ f2n_w^T + biases  -> fp16 node states [B*9, 256]
    gemm_mma<1><<<dim3((NN * HID) / 128, B_SZ / 128), 128, SMEM_DYN>>>(
        X, W1, FDIM, nullptr, 0,
        ns, f2n_b, enc_b, enc_w, logits);

    for (int s = 0; s < 4; ++s) {
        // Y = ns @ Wc^T : [B*9, 256] x [512, 256]^T -> [B*9, 512] fp16
        gemm_mma<0><<<dim3(512 / 128, BROWS / 128), 128, SMEM_DYN>>>(
            ns, W2, HID, Y, 512,
            nullptr, nullptr, nullptr, nullptr, nullptr);
        if (s < 3)
            combine_kernel<<<B_SZ, 256>>>(ns, Y);
        else
            final_kernel<<<B_SZ, 64>>>(Y, out_w, out_b, out);
    }
}